// round 16
// baseline (speedup 1.0000x reference)
#include <cuda_runtime.h>
#include <cuda_bf16.h>

// Scratch (no dynamic allocation allowed). B = 8192 here; headroom.
#define MAX_ROWS 16384
__device__ float        g_row_loss[MAX_ROWS];
__device__ unsigned int g_ticket;   // zero-initialized; self-resets via atomicInc wrap

// ---------------------------------------------------------------------------
// One CTA per row. S = sum_c exp(y[b,c]) via streaming float4 loads, then
// loss_b = log1p((S - exp(y_t)) * exp(-y_t)). The LAST CTA to finish
// (atomicInc ticket, wraps to 0 at B-1 so it self-resets each launch)
// performs the deterministic fixed-order mean over row_loss and writes out.
//
// Label dtype (int64 vs int32 layout) is detected inline by warp 0: lanes
// check the first up-to-64 int64 interpretations against [0, C). A packed
// int32 buffer passes with prob ~(1/C)^64 ~ 0. Probed bytes (<=512 B) are
// in bounds under either dtype.
// ---------------------------------------------------------------------------
template <int BLOCK>
__global__ __launch_bounds__(BLOCK) void sup_contrastive_fused_kernel(
    const float* __restrict__ y_pred,
    const void*  __restrict__ y_true,
    float* __restrict__ row_loss,
    unsigned int* __restrict__ ticket,
    float* __restrict__ out,
    int C)
{
    const int b = blockIdx.x;
    const int B = gridDim.x;
    const float* row = y_pred + (size_t)b * (size_t)C;

    // 4 independent accumulators to break the FADD dependency chain.
    float s0 = 0.f, s1 = 0.f, s2 = 0.f, s3 = 0.f;

    const int n4 = C >> 2;           // C = 32000 -> 8000 float4, 16B aligned
    const float4* row4 = reinterpret_cast<const float4*>(row);

    #pragma unroll 8
    for (int i = threadIdx.x; i < n4; i += BLOCK) {
        float4 v = __ldcs(&row4[i]);   // streaming: data read exactly once
        s0 += __expf(v.x);
        s1 += __expf(v.y);
        s2 += __expf(v.z);
        s3 += __expf(v.w);
    }
    // Scalar tail (no-op for C = 32000).
    for (int i = (n4 << 2) + threadIdx.x; i < C; i += BLOCK) {
        s0 += __expf(__ldcs(&row[i]));
    }

    float s = (s0 + s1) + (s2 + s3);

    // Warp reduce
    #pragma unroll
    for (int off = 16; off > 0; off >>= 1)
        s += __shfl_down_sync(0xFFFFFFFFu, s, off);

    __shared__ float warp_sums[BLOCK / 32];
    __shared__ int   s_is_last;
    const int lane = threadIdx.x & 31;
    const int wid  = threadIdx.x >> 5;
    if (lane == 0) warp_sums[wid] = s;
    __syncthreads();

    if (wid == 0) {
        s = (lane < BLOCK / 32) ? warp_sums[lane] : 0.f;
        #pragma unroll
        for (int off = (BLOCK / 64); off > 0; off >>= 1)
            s += __shfl_down_sync(0xFFFFFFFFu, s, off);

        // ---- inline dtype probe (whole warp, ballot) ----
        const int n64 = max(1, min(64, B >> 1));
        const long long* p64 = (const long long*)y_true;
        int bad = 0;
        #pragma unroll
        for (int j = lane; j < 64; j += 32) {
            if (j < n64) {
                long long v = p64[j];
                if (v < 0 || v >= (long long)C) bad = 1;
            }
        }
        const int is64 = (__ballot_sync(0xFFFFFFFFu, bad) == 0u);

        if (lane == 0) {
            int t = is64 ? (int)p64[b] : ((const int*)y_true)[b];
            // Defensive clamp: a wrong dtype guess must not fault.
            if (t < 0) t = 0; if (t >= C) t = C - 1;

            const float yt = row[t];
            const float et = __expf(yt);
            // negatives sum = S - exp(y_t); positive factor = exp(-y_t)
            row_loss[b] = log1pf((s - et) * __expf(-yt));

            // Release our row_loss store, then draw a ticket. atomicInc
            // wraps to 0 at B-1 -> counter self-resets for the next launch.
            __threadfence();
            unsigned int old = atomicInc(ticket, (unsigned int)(B - 1));
            s_is_last = (old == (unsigned int)(B - 1)) ? 1 : 0;
        }
    }
    __syncthreads();

    // ---- last CTA: deterministic fixed-order mean over row_loss ----
    if (s_is_last) {
        float r = 0.f;
        const int m4 = B >> 2;
        const float4* rl4 = reinterpret_cast<const float4*>(row_loss);
        for (int i = threadIdx.x; i < m4; i += BLOCK) {
            float4 v = rl4[i];
            r += (v.x + v.y) + (v.z + v.w);
        }
        for (int i = (m4 << 2) + threadIdx.x; i < B; i += BLOCK)
            r += row_loss[i];

        #pragma unroll
        for (int off = 16; off > 0; off >>= 1)
            r += __shfl_down_sync(0xFFFFFFFFu, r, off);

        __shared__ float fin_sums[BLOCK / 32];
        if (lane == 0) fin_sums[wid] = r;
        __syncthreads();

        if (wid == 0) {
            r = (lane < BLOCK / 32) ? fin_sums[lane] : 0.f;
            #pragma unroll
            for (int off = (BLOCK / 64); off > 0; off >>= 1)
                r += __shfl_down_sync(0xFFFFFFFFu, r, off);
            if (lane == 0)
                out[0] = r / (float)B;
        }
    }
}

// ---------------------------------------------------------------------------
// Entry point. y_pred identified as the LARGER input (robust to metadata
// ordering). Output: single fp32 scalar.
// ---------------------------------------------------------------------------
extern "C" void kernel_launch(void* const* d_in, const int* in_sizes, int n_in,
                              void* d_out, int out_size)
{
    const int i_pred = (in_sizes[0] >= in_sizes[1]) ? 0 : 1;
    const int i_true = 1 - i_pred;

    const float* y_pred = (const float*)d_in[i_pred];
    const void*  y_true = d_in[i_true];
    float* out = (float*)d_out;

    const int B = in_sizes[i_true];
    const int C = in_sizes[i_pred] / B;

    // One-time symbol lookups (pure address queries; capture-safe, no alloc).
    static float*        row_loss = nullptr;
    static unsigned int* ticket   = nullptr;
    if (row_loss == nullptr) {
        cudaGetSymbolAddress((void**)&row_loss, g_row_loss);
        cudaGetSymbolAddress((void**)&ticket,   g_ticket);
    }

    constexpr int BLOCK = 256;
    sup_contrastive_fused_kernel<BLOCK><<<B, BLOCK>>>(
        y_pred, y_true, row_loss, ticket, out, C);
}